// round 1
// baseline (speedup 1.0000x reference)
#include <cuda_runtime.h>
#include <cuda_bf16.h>

// Problem: B=8, C=256, O=256, H=64, W=64.
// out[b,o,h,w] = sum_{k=0..2303} Wc[o,k] * X[k](b,h,w)
//   k <  256 : X = feat[b, k, h, w]
//   k >= 256 : s = k/256 - 1, c = k%256,
//              X = feat[b, c, sy[h,w,s]-1, sx[h,w,s]-1]   (indices always in-bounds)

#define C_    256
#define KTOT  2304
#define H_    64
#define W_    64
#define BM    256   // all of O
#define BN    64    // one image row (fixed h, w = 0..63)
#define BK    16

__global__ __launch_bounds__(256, 2)
void gfd_kernel(const float* __restrict__ feat,
                const float* __restrict__ Wc,
                const int*   __restrict__ sx,
                const int*   __restrict__ sy,
                float*       __restrict__ out)
{
    __shared__ float Ws[BK][BM];      // 16 KB, [k][o] (transposed for contiguous o reads)
    __shared__ float Xs[BK][BN];      // 4 KB
    __shared__ int   goff[8][BN];     // gather offsets per sample per w

    const int h   = blockIdx.x & 63;
    const int b   = blockIdx.x >> 6;
    const int tid = threadIdx.x;

    // Precompute gather offsets for this (h) row: goff[s][w] = (y-1)*64 + (x-1)
    for (int t = tid; t < 8 * BN; t += 256) {
        const int s = t >> 6;
        const int w = t & 63;
        const int idx = (h * W_ + w) * 8 + s;
        goff[s][w] = (sy[idx] - 1) * W_ + (sx[idx] - 1);
    }
    __syncthreads();

    const float* fb = feat + (size_t)b * C_ * (H_ * W_);

    float acc[8][8];
#pragma unroll
    for (int i = 0; i < 8; i++)
#pragma unroll
        for (int j = 0; j < 8; j++) acc[i][j] = 0.0f;

    // compute-thread mapping: to = tid/8 -> o block, tn = tid%8 -> n block
    const int ob = (tid >> 3) * 8;   // 0..248
    const int nb = (tid & 7) * 8;    // 0..56

    // X-load mapping: row r = tid/16 (0..15), cols xn..xn+3
    const int xr = tid >> 4;
    const int xn = (tid & 15) << 2;

    for (int kt = 0; kt < KTOT / BK; kt++) {
        const int k0 = kt * BK;

        // ---- stage W tile: thread tid owns output row o = tid ----
        {
            const float* wrow = Wc + (size_t)tid * KTOT + k0;
#pragma unroll
            for (int q = 0; q < 4; q++) {
                const float4 v = *(const float4*)(wrow + q * 4);
                Ws[q * 4 + 0][tid] = v.x;
                Ws[q * 4 + 1][tid] = v.y;
                Ws[q * 4 + 2][tid] = v.z;
                Ws[q * 4 + 3][tid] = v.w;
            }
        }

        // ---- stage X tile (gather) ----
        {
            const int k    = k0 + xr;
            const int sidx = k >> 8;       // 0 = identity, 1..8 = gathered sample
            const int c    = k & 255;
            const float* plane = fb + (size_t)c * (H_ * W_);
            if (sidx == 0) {
                *(float4*)&Xs[xr][xn] = *(const float4*)(plane + h * W_ + xn);
            } else {
                const int* go = goff[sidx - 1];
                Xs[xr][xn + 0] = plane[go[xn + 0]];
                Xs[xr][xn + 1] = plane[go[xn + 1]];
                Xs[xr][xn + 2] = plane[go[xn + 2]];
                Xs[xr][xn + 3] = plane[go[xn + 3]];
            }
        }
        __syncthreads();

        // ---- 8x8 micro-tile FFMA ----
#pragma unroll
        for (int k = 0; k < BK; k++) {
            float a[8], bv[8];
            *(float4*)&a[0]  = *(const float4*)&Ws[k][ob];
            *(float4*)&a[4]  = *(const float4*)&Ws[k][ob + 4];
            *(float4*)&bv[0] = *(const float4*)&Xs[k][nb];
            *(float4*)&bv[4] = *(const float4*)&Xs[k][nb + 4];
#pragma unroll
            for (int i = 0; i < 8; i++)
#pragma unroll
                for (int j = 0; j < 8; j++)
                    acc[i][j] = fmaf(a[i], bv[j], acc[i][j]);
        }
        __syncthreads();
    }

    // ---- store: out[b][o][h][w] ----
#pragma unroll
    for (int i = 0; i < 8; i++) {
        const int o = ob + i;
        float* orow = out + ((((size_t)b * 256 + o) * 64 + h) * 64 + nb);
        *(float4*)(orow)     = make_float4(acc[i][0], acc[i][1], acc[i][2], acc[i][3]);
        *(float4*)(orow + 4) = make_float4(acc[i][4], acc[i][5], acc[i][6], acc[i][7]);
    }
}

extern "C" void kernel_launch(void* const* d_in, const int* in_sizes, int n_in,
                              void* d_out, int out_size)
{
    const float* feat = (const float*)d_in[0];   // (8,256,64,64) f32
    const float* Wc   = (const float*)d_in[1];   // (256,2304) f32
    const int*   sx   = (const int*)d_in[2];     // (64,64,8) i32
    const int*   sy   = (const int*)d_in[3];     // (64,64,8) i32
    float*       out  = (float*)d_out;           // (8,256,64,64) f32

    // grid: one CTA per (b, h) row: 8*64 = 512 CTAs
    gfd_kernel<<<512, 256>>>(feat, Wc, sx, sy, out);
}

// round 3
// speedup vs baseline: 3.3479x; 3.3479x over previous
#include <cuda_runtime.h>
#include <cuda_bf16.h>
#include <cstdint>

// ============================================================================
// GFDreConv: out[b,o,h,w] = sum_{k<2304} W[o,k] * X[k](b,h,w)
//   k<256: X = feat[b,k,h,w];  else s=k/256-1, c=k%256,
//   X = feat[b,c,sy-1,sx-1] (coords are clip()+1 -> always in-bounds).
// Gather offset depends only on (spatial, s) -> transpose feat to [b][sp][c],
// then every K-run is contiguous. GEMM via mma.sync m16n8k16 bf16 with
// 3-term hi/lo split (fp32 accum): rel_err ~1e-6.
// ============================================================================

#define KTOT 2304
#define BM   128
#define BN   128
#define BK   32
#define NC   (KTOT / BK)   // 72

__device__ __align__(16) __nv_bfloat16 g_Whi[256 * KTOT];
__device__ __align__(16) __nv_bfloat16 g_Wlo[256 * KTOT];
__device__ __align__(16) __nv_bfloat16 g_Fhi[8ull * 4096 * 256];
__device__ __align__(16) __nv_bfloat16 g_Flo[8ull * 4096 * 256];

// smem: rows padded to 40 halves (80B) -> ldmatrix phase stride 5 (16B units),
// coprime with 8 banks => conflict-free.
#define LDS_ROW 40
#define BUF_H   (128 * LDS_ROW)           // halves per buffer (10240 B)
#define OFF_AH  0
#define OFF_AL  20480
#define OFF_BH  40960
#define OFF_BL  61440
#define OFF_GO  81920                      // 9*128 ints
#define SMEM_TOTAL (OFF_GO + 9 * 128 * 4)  // 86528 B

__device__ __forceinline__ uint32_t s2u(const void* p) {
    uint32_t a;
    asm("{ .reg .u64 t; cvta.to.shared.u64 t, %1; cvt.u32.u64 %0, t; }" : "=r"(a) : "l"(p));
    return a;
}
__device__ __forceinline__ void cpa(uint32_t d, const void* g) {
    asm volatile("cp.async.cg.shared.global [%0], [%1], 16;" :: "r"(d), "l"(g));
}

#define LDSM4(r, a)                                                            \
    asm volatile("ldmatrix.sync.aligned.m8n8.x4.shared.b16 {%0,%1,%2,%3},[%4];"\
                 : "=r"((r)[0]), "=r"((r)[1]), "=r"((r)[2]), "=r"((r)[3])      \
                 : "r"(a))
#define LDSM2(r0, r1, a)                                                       \
    asm volatile("ldmatrix.sync.aligned.m8n8.x2.shared.b16 {%0,%1},[%2];"      \
                 : "=r"(r0), "=r"(r1) : "r"(a))
#define MMA(c, a, b0, b1)                                                      \
    asm volatile("mma.sync.aligned.m16n8k16.row.col.f32.bf16.bf16.f32 "        \
                 "{%0,%1,%2,%3},{%4,%5,%6,%7},{%8,%9},{%0,%1,%2,%3};"          \
                 : "+f"((c)[0]), "+f"((c)[1]), "+f"((c)[2]), "+f"((c)[3])      \
                 : "r"((a)[0]), "r"((a)[1]), "r"((a)[2]), "r"((a)[3]),         \
                   "r"(b0), "r"(b1))

// ---------------------------------------------------------------------------
// Prep 1: split W into bf16 hi/lo (plain row-major [o][k]).
// ---------------------------------------------------------------------------
__global__ void w_prep(const float* __restrict__ Wc) {
    int idx = blockIdx.x * 256 + threadIdx.x;  // 256*2304 total
    float v = Wc[idx];
    __nv_bfloat16 hi = __float2bfloat16(v);
    __nv_bfloat16 lo = __float2bfloat16(v - __bfloat162float(hi));
    g_Whi[idx] = hi;
    g_Wlo[idx] = lo;
}

// ---------------------------------------------------------------------------
// Prep 2: transpose feat [b][c][y][x] -> [b][y*64+x][c], bf16 hi/lo.
// ---------------------------------------------------------------------------
__global__ void f_prep(const float* __restrict__ feat) {
    __shared__ float tile[32][65];
    int b = blockIdx.x >> 6;
    int y = blockIdx.x & 63;
    int t = threadIdx.x;
    for (int c0 = 0; c0 < 256; c0 += 32) {
        int x2 = (t & 31) * 2;
        int cb = (t >> 5) * 4;
#pragma unroll
        for (int ii = 0; ii < 4; ii++) {
            int ci = cb + ii;
            float2 v = *(const float2*)&feat[(((size_t)b * 256 + c0 + ci) * 64 + y) * 64 + x2];
            tile[ci][x2] = v.x;
            tile[ci][x2 + 1] = v.y;
        }
        __syncthreads();
        int ci = t & 31;
#pragma unroll
        for (int jj = 0; jj < 8; jj++) {
            int x = (t >> 5) + jj * 8;
            float v = tile[ci][x];
            __nv_bfloat16 hi = __float2bfloat16(v);
            __nv_bfloat16 lo = __float2bfloat16(v - __bfloat162float(hi));
            size_t off = ((size_t)b * 4096 + (size_t)y * 64 + x) * 256 + c0 + ci;
            g_Fhi[off] = hi;
            g_Flo[off] = lo;
        }
        __syncthreads();
    }
}

// ---------------------------------------------------------------------------
// Main: 512 CTAs (2 M-blocks x 256 N-blocks), 256 threads (8 warps, 4Mx2N).
// ---------------------------------------------------------------------------
__global__ void __launch_bounds__(256)
gfd_mma(const int* __restrict__ sx, const int* __restrict__ sy,
        float* __restrict__ out) {
    extern __shared__ char sm[];
    const uint32_t sb = s2u(sm);

    const int t = threadIdx.x, lane = t & 31, wid = t >> 5;
    const int wm = wid & 3, wn = wid >> 2;
    const int mblk = blockIdx.x & 1, nblk = blockIdx.x >> 1;
    const int b = nblk >> 5;
    const int sp0 = (nblk & 31) * 128;

    // gather table: gofs[s][nn] = spatial row in featT (s=0 identity)
    int* gofs = (int*)(sm + OFF_GO);
    for (int i = t; i < 9 * 128; i += 256) {
        int s = i >> 7, nn = i & 127;
        int sp = sp0 + nn;
        int v;
        if (s == 0) v = sp;
        else {
            int idx = sp * 8 + (s - 1);
            v = (sy[idx] - 1) * 64 + (sx[idx] - 1);
        }
        gofs[i] = v;
    }
    __syncthreads();

    const int arow = t >> 2;      // 0..63 (two rows per thread: arow, arow+64)
    const int ach = t & 3;        // 16B chunk within 64B row
    const size_t fb = (size_t)b * 4096 * 256;
    const __nv_bfloat16* wHbase = g_Whi + (size_t)(mblk * 128) * KTOT;
    const __nv_bfloat16* wLbase = g_Wlo + (size_t)(mblk * 128) * KTOT;

    float acc[2][8][4];
#pragma unroll
    for (int i = 0; i < 2; i++)
#pragma unroll
        for (int j = 0; j < 8; j++)
#pragma unroll
            for (int q = 0; q < 4; q++) acc[i][j][q] = 0.0f;

    // ---- async stage of chunk kc into buffer buf ----
    auto issue = [&](int kc, int buf) {
        const int k0 = kc * BK;
        const int s = kc >> 3;
        const int c0 = (kc & 7) * 32;
        const uint32_t bufh = (uint32_t)buf * BUF_H;
#pragma unroll
        for (int j = 0; j < 2; j++) {
            const int row = arow + j * 64;
            const uint32_t doff = (bufh + (uint32_t)row * LDS_ROW + ach * 8) * 2;
            cpa(sb + OFF_AH + doff, wHbase + (size_t)row * KTOT + k0 + ach * 8);
            cpa(sb + OFF_AL + doff, wLbase + (size_t)row * KTOT + k0 + ach * 8);
            const int sp = gofs[s * 128 + row];
            const size_t fo = fb + (size_t)sp * 256 + c0 + ach * 8;
            cpa(sb + OFF_BH + doff, g_Fhi + fo);
            cpa(sb + OFF_BL + doff, g_Flo + fo);
        }
        asm volatile("cp.async.commit_group;" ::: "memory");
    };

    issue(0, 0);
    int buf = 0;

    for (int kc = 0; kc < NC; kc++) {
        if (kc + 1 < NC) {
            issue(kc + 1, buf ^ 1);
            asm volatile("cp.async.wait_group 1;" ::: "memory");
        } else {
            asm volatile("cp.async.wait_group 0;" ::: "memory");
        }
        __syncthreads();

        const uint32_t aH = sb + OFF_AH + (uint32_t)buf * BUF_H * 2;
        const uint32_t aL = sb + OFF_AL + (uint32_t)buf * BUF_H * 2;
        const uint32_t bH = sb + OFF_BH + (uint32_t)buf * BUF_H * 2;
        const uint32_t bL = sb + OFF_BL + (uint32_t)buf * BUF_H * 2;

#pragma unroll
        for (int kk = 0; kk < 2; kk++) {           // two k16 halves of BK=32
            uint32_t ah[2][4], al[2][4];
#pragma unroll
            for (int i = 0; i < 2; i++) {
                const int row = wm * 32 + i * 16 + (lane & 15);
                const uint32_t off =
                    ((uint32_t)row * LDS_ROW + kk * 16 + (lane >> 4) * 8) * 2;
                LDSM4(ah[i], aH + off);
                LDSM4(al[i], aL + off);
            }
#pragma unroll
            for (int j = 0; j < 8; j++) {
                const int rowb = wn * 64 + j * 8 + (lane & 7);
                const uint32_t off =
                    ((uint32_t)rowb * LDS_ROW + kk * 16 + ((lane >> 3) & 1) * 8) * 2;
                uint32_t bh0, bh1, bl0, bl1;
                LDSM2(bh0, bh1, bH + off);
                LDSM2(bl0, bl1, bL + off);
#pragma unroll
                for (int i = 0; i < 2; i++) {
                    MMA(acc[i][j], ah[i], bh0, bh1);
                    MMA(acc[i][j], ah[i], bl0, bl1);
                    MMA(acc[i][j], al[i], bh0, bh1);
                }
            }
        }
        __syncthreads();
        buf ^= 1;
    }

    // ---- epilogue: float2 stores straight to out[b][o][sp] ----
    const int g = lane >> 2, tig = lane & 3;
#pragma unroll
    for (int i = 0; i < 2; i++) {
        const int o = mblk * 128 + wm * 32 + i * 16 + g;
        float* obase = out + ((size_t)b * 256 + o) * 4096;
#pragma unroll
        for (int j = 0; j < 8; j++) {
            const int sp = sp0 + wn * 64 + j * 8 + tig * 2;
            *(float2*)(obase + sp) = make_float2(acc[i][j][0], acc[i][j][1]);
            *(float2*)(obase + 8 * 4096 + sp) = make_float2(acc[i][j][2], acc[i][j][3]);
        }
    }
}

// ============================================================================
extern "C" void kernel_launch(void* const* d_in, const int* in_sizes, int n_in,
                              void* d_out, int out_size) {
    const float* feat = (const float*)d_in[0];  // (8,256,64,64) f32
    const float* Wc   = (const float*)d_in[1];  // (256,2304) f32
    const int*   sx   = (const int*)d_in[2];    // (64,64,8) i32
    const int*   sy   = (const int*)d_in[3];    // (64,64,8) i32
    float*       out  = (float*)d_out;          // (8,256,64,64) f32

    static bool attr_set = false;
    if (!attr_set) {
        cudaFuncSetAttribute(gfd_mma, cudaFuncAttributeMaxDynamicSharedMemorySize,
                             SMEM_TOTAL);
        attr_set = true;
    }

    w_prep<<<2304, 256>>>(Wc);
    f_prep<<<512, 256>>>(feat);
    gfd_mma<<<512, 256, SMEM_TOTAL>>>(sx, sy, out);
}